// round 2
// baseline (speedup 1.0000x reference)
#include <cuda_runtime.h>

// Problem constants: S=2048, B=32, D=256, H=4.  M = S*B = 65536 rows.
#define MROWS 65536
#define DK    256

static constexpr size_t MD_ = (size_t)MROWS * DK;   // 16,777,216 floats (64 MB)

// Scratch pool: 8 big buffers (q/k/v ping-pong + 2 scratch) + small region.
// 8*MD + 1M floats  = ~541 MB static device memory (allowed: __device__ global).
__device__ float g_pool[8ull * 16777216ull + 1048576ull];

// small-region offsets (floats, relative to pool start)
static constexpr size_t O_SMALL = 8ull * 16777216ull;
static constexpr size_t O_SSUM  = O_SMALL;
static constexpr size_t O_SSQ   = O_SMALL + 256;
static constexpr size_t O_SCALE = O_SMALL + 512;
static constexpr size_t O_SHIFT = O_SMALL + 768;
static constexpr size_t O_PM    = O_SMALL + 1024;
static constexpr size_t O_PZ    = O_PM + 16 * 32 * 256;
static constexpr size_t O_PA    = O_PZ + 16 * 32 * 256;
static constexpr size_t O_XCAT  = O_PA + 16 * 32 * 256;     // [32, 1024]
static constexpr size_t O_H0    = O_XCAT + 32 * 1024;       // [32, 256]
static constexpr size_t O_H1    = O_H0 + 32 * 256;          // [32, 256]

// ---------------------------------------------------------------------------
// GEMM: C[M,256] = act(A)[M,256] @ W[256,256]^T + bias
// act(a) = relu(a*ascale[k] + ashift[k])  if ascale != nullptr (fused BN+ReLU
// on the *input* channels), else identity.
// Block tile 128x128, 256 threads, 8x8 micro-tile, K chunked by 16.
// ---------------------------------------------------------------------------
__global__ __launch_bounds__(256, 2)
void gemm_nt(const float* __restrict__ A, const float* __restrict__ Wm,
             const float* __restrict__ bias,
             const float* __restrict__ ascale, const float* __restrict__ ashift,
             float* __restrict__ C)
{
    __shared__ float As[16][132];
    __shared__ float Bs[16][132];
    const int t  = threadIdx.x;
    const int r0 = blockIdx.x * 128;
    const int c0 = blockIdx.y * 128;
    const int lr = t >> 2;          // 0..63  (row within half-tile for loads)
    const int lk = (t & 3) << 2;    // 0,4,8,12 (k quad for loads)
    const int tr = t >> 4;          // 0..15
    const int tc = t & 15;          // 0..15

    float acc[8][8];
#pragma unroll
    for (int i = 0; i < 8; i++)
#pragma unroll
        for (int j = 0; j < 8; j++) acc[i][j] = 0.f;

    const bool bn = (ascale != nullptr);

    for (int kc = 0; kc < 256; kc += 16) {
        float4 sc, sh;
        if (bn) {
            sc = *(const float4*)(ascale + kc + lk);
            sh = *(const float4*)(ashift + kc + lk);
        }
#pragma unroll
        for (int h = 0; h < 2; h++) {
            int row = lr + (h << 6);
            float4 a = *(const float4*)(A + (size_t)(r0 + row) * 256 + kc + lk);
            if (bn) {
                a.x = fmaxf(fmaf(a.x, sc.x, sh.x), 0.f);
                a.y = fmaxf(fmaf(a.y, sc.y, sh.y), 0.f);
                a.z = fmaxf(fmaf(a.z, sc.z, sh.z), 0.f);
                a.w = fmaxf(fmaf(a.w, sc.w, sh.w), 0.f);
            }
            As[lk + 0][row] = a.x; As[lk + 1][row] = a.y;
            As[lk + 2][row] = a.z; As[lk + 3][row] = a.w;
            float4 b = *(const float4*)(Wm + (size_t)(c0 + row) * 256 + kc + lk);
            Bs[lk + 0][row] = b.x; Bs[lk + 1][row] = b.y;
            Bs[lk + 2][row] = b.z; Bs[lk + 3][row] = b.w;
        }
        __syncthreads();
#pragma unroll
        for (int kk = 0; kk < 16; kk++) {
            float a[8], b[8];
            *(float4*)(a)     = *(const float4*)&As[kk][tr * 4];
            *(float4*)(a + 4) = *(const float4*)&As[kk][tr * 4 + 64];
            *(float4*)(b)     = *(const float4*)&Bs[kk][tc * 4];
            *(float4*)(b + 4) = *(const float4*)&Bs[kk][tc * 4 + 64];
#pragma unroll
            for (int i = 0; i < 8; i++)
#pragma unroll
                for (int j = 0; j < 8; j++)
                    acc[i][j] = fmaf(a[i], b[j], acc[i][j]);
        }
        __syncthreads();
    }

    float4 b0 = *(const float4*)(bias + c0 + tc * 4);
    float4 b1 = *(const float4*)(bias + c0 + tc * 4 + 64);
#pragma unroll
    for (int i = 0; i < 8; i++) {
        int row = r0 + tr * 4 + (i & 3) + ((i >> 2) << 6);
        float4 o0 = make_float4(acc[i][0] + b0.x, acc[i][1] + b0.y,
                                acc[i][2] + b0.z, acc[i][3] + b0.w);
        float4 o1 = make_float4(acc[i][4] + b1.x, acc[i][5] + b1.y,
                                acc[i][6] + b1.z, acc[i][7] + b1.w);
        *(float4*)(C + (size_t)row * 256 + c0 + tc * 4)      = o0;
        *(float4*)(C + (size_t)row * 256 + c0 + tc * 4 + 64) = o1;
    }
}

// W = K - Q   (elementwise, float4)
__global__ void subk(const float4* __restrict__ K, const float4* __restrict__ Q,
                     float4* __restrict__ W)
{
    size_t i = (size_t)blockIdx.x * blockDim.x + threadIdx.x;
    float4 k = K[i], q = Q[i];
    W[i] = make_float4(k.x - q.x, k.y - q.y, k.z - q.z, k.w - q.w);
}

__global__ void zerok(float* a, float* b)
{
    a[threadIdx.x] = 0.f;
    b[threadIdx.x] = 0.f;
}

// Per-channel sum and sum-of-squares over all 65536 rows (256 rows per block).
__global__ void colstats(const float* __restrict__ X, float* __restrict__ s,
                         float* __restrict__ sq)
{
    int c = threadIdx.x;
    size_t base = (size_t)blockIdx.x * 256 * 256 + c;
    float a = 0.f, b = 0.f;
#pragma unroll 8
    for (int i = 0; i < 256; i++) {
        float x = X[base + (size_t)i * 256];
        a += x;
        b = fmaf(x, x, b);
    }
    atomicAdd(&s[c], a);
    atomicAdd(&sq[c], b);
}

// scale = rstd*gamma ; shift = beta - mean*rstd*gamma   (biased variance, eps=1e-5)
__global__ void bnfinal(const float* __restrict__ s, const float* __restrict__ sq,
                        const float* __restrict__ gamma, const float* __restrict__ beta,
                        float* __restrict__ scale, float* __restrict__ shift)
{
    int c = threadIdx.x;
    const float inv = 1.f / 65536.f;
    float m = s[c] * inv;
    float v = sq[c] * inv - m * m;
    float r = rsqrtf(v + 1e-5f);
    float sc = r * gamma[c];
    scale[c] = sc;
    shift[c] = beta[c] - m * sc;
}

// Online softmax over S (split into 16 chunks of 128) fused with weighted V-sum.
// Each thread owns one (b, d) column; no cross-thread reduction needed.
__global__ void smax_part(const float* __restrict__ W3, const float* __restrict__ V,
                          float* __restrict__ pm, float* __restrict__ pz,
                          float* __restrict__ pa)
{
    int b = blockIdx.x, ch = blockIdx.y, d = threadIdx.x;
    float m = -1e30f, Z = 0.f, acc = 0.f;
#pragma unroll 4
    for (int j = 0; j < 128; j++) {
        int s_ = ch * 128 + j;
        size_t idx = ((size_t)(s_ * 32 + b)) * 256 + d;
        float w = W3[idx];
        float v = V[idx];
        float nm = fmaxf(m, w);
        float e0 = __expf(m - nm);
        float e1 = __expf(w - nm);
        Z   = Z * e0 + e1;
        acc = fmaf(v, e1, acc * e0);
        m = nm;
    }
    int o = (ch * 32 + b) * 256 + d;
    pm[o] = m; pz[o] = Z; pa[o] = acc;
}

__global__ void smax_comb(const float* __restrict__ pm, const float* __restrict__ pz,
                          const float* __restrict__ pa, float* __restrict__ xcat,
                          int head)
{
    int b = blockIdx.x, d = threadIdx.x;
    float m = -1e30f, Z = 0.f, acc = 0.f;
#pragma unroll
    for (int ch = 0; ch < 16; ch++) {
        int o = (ch * 32 + b) * 256 + d;
        float cm = pm[o];
        float nm = fmaxf(m, cm);
        float e0 = __expf(m - nm);
        float e1 = __expf(cm - nm);
        Z   = Z * e0 + pz[o] * e1;
        acc = acc * e0 + pa[o] * e1;
        m = nm;
    }
    xcat[b * 1024 + head * 256 + d] = acc / Z;
}

// Tiny MLP layer: Y[32,256] = act(X[32,Kdim] @ Wm[256,Kdim]^T + bias)
__global__ void mlp_k(const float* __restrict__ X, const float* __restrict__ Wm,
                      const float* __restrict__ bias, float* __restrict__ Y,
                      int Kdim, int do_relu)
{
    __shared__ float sx[1024];
    int b = blockIdx.x, c = threadIdx.x;
    for (int t = c; t < Kdim; t += 256) sx[t] = X[b * Kdim + t];
    __syncthreads();
    float s = 0.f;
#pragma unroll 4
    for (int t = 0; t < Kdim; t++) s = fmaf(sx[t], Wm[c * Kdim + t], s);
    s += bias[c];
    if (do_relu) s = fmaxf(s, 0.f);
    Y[b * 256 + c] = s;
}

// ---------------------------------------------------------------------------
extern "C" void kernel_launch(void* const* d_in, const int* in_sizes, int n_in,
                              void* d_out, int out_size)
{
    float* pool = nullptr;
    cudaGetSymbolAddress((void**)&pool, g_pool);

    const float* q   = (const float*)d_in[0];
    const float* k   = (const float*)d_in[1];
    const float* v   = (const float*)d_in[2];
    const float* wq  = (const float*)d_in[3];
    const float* bq  = (const float*)d_in[4];
    const float* wk  = (const float*)d_in[5];
    const float* bk  = (const float*)d_in[6];
    const float* wv  = (const float*)d_in[7];
    const float* bv  = (const float*)d_in[8];
    const float* g1  = (const float*)d_in[9];
    const float* be1 = (const float*)d_in[10];
    const float* wl1 = (const float*)d_in[11];
    const float* bl1 = (const float*)d_in[12];
    const float* g2  = (const float*)d_in[13];
    const float* be2 = (const float*)d_in[14];
    const float* wl2 = (const float*)d_in[15];
    const float* bl2 = (const float*)d_in[16];
    const float* mw0 = (const float*)d_in[17];
    const float* mb0 = (const float*)d_in[18];
    const float* mw1 = (const float*)d_in[19];
    const float* mb1 = (const float*)d_in[20];
    const float* mw2 = (const float*)d_in[21];
    const float* mb2 = (const float*)d_in[22];

    float* Qb[2] = {pool + 0 * MD_, pool + 1 * MD_};
    float* Kb[2] = {pool + 2 * MD_, pool + 3 * MD_};
    float* Vb[2] = {pool + 4 * MD_, pool + 5 * MD_};
    float* W     = pool + 6 * MD_;
    float* W2    = pool + 7 * MD_;
    float* ssum  = pool + O_SSUM;
    float* ssq   = pool + O_SSQ;
    float* scale = pool + O_SCALE;
    float* shift = pool + O_SHIFT;
    float* pm    = pool + O_PM;
    float* pz    = pool + O_PZ;
    float* pa    = pool + O_PA;
    float* xcat  = pool + O_XCAT;
    float* h0    = pool + O_H0;
    float* h1    = pool + O_H1;

    dim3 gg(MROWS / 128, 2);   // 512 x 2 blocks

    for (int i = 0; i < 4; i++) {
        const float* Qs = i ? Qb[(i - 1) & 1] : q;
        const float* Ks = i ? Kb[(i - 1) & 1] : k;
        const float* Vs = i ? Vb[(i - 1) & 1] : v;
        float* Qd = Qb[i & 1];
        float* Kd = Kb[i & 1];
        float* Vd = Vb[i & 1];

        gemm_nt<<<gg, 256>>>(Qs, wq + i * 65536, bq + i * 256, nullptr, nullptr, Qd);
        gemm_nt<<<gg, 256>>>(Ks, wk + i * 65536, bk + i * 256, nullptr, nullptr, Kd);
        gemm_nt<<<gg, 256>>>(Vs, wv + i * 65536, bv + i * 256, nullptr, nullptr, Vd);

        subk<<<16384, 256>>>((const float4*)Kd, (const float4*)Qd, (float4*)W);

        zerok<<<1, 256>>>(ssum, ssq);
        colstats<<<256, 256>>>(W, ssum, ssq);
        bnfinal<<<1, 256>>>(ssum, ssq, g1 + i * 256, be1 + i * 256, scale, shift);

        gemm_nt<<<gg, 256>>>(W, wl1 + i * 65536, bl1 + i * 256, scale, shift, W2);

        zerok<<<1, 256>>>(ssum, ssq);
        colstats<<<256, 256>>>(W2, ssum, ssq);
        bnfinal<<<1, 256>>>(ssum, ssq, g2 + i * 256, be2 + i * 256, scale, shift);

        gemm_nt<<<gg, 256>>>(W2, wl2 + i * 65536, bl2 + i * 256, scale, shift, W);

        smax_part<<<dim3(32, 16), 256>>>(W, Vd, pm, pz, pa);
        smax_comb<<<32, 256>>>(pm, pz, pa, xcat, i);
    }

    mlp_k<<<32, 256>>>(xcat, mw0, mb0, h0, 1024, 1);
    mlp_k<<<32, 256>>>(h0, mw1, mb1, h1, 256, 1);
    mlp_k<<<32, 256>>>(h1, mw2, mb2, (float*)d_out, 256, 0);
}